// round 15
// baseline (speedup 1.0000x reference)
#include <cuda_runtime.h>
#include <cuda_bf16.h>

#define BATCH 8192
#define TT 128
#define ZT 129
#define FLAT 16512
#define NQ 1024
#define KT 129          // per K-split: 4128 = 129*32
#define KSPLIT 4
#define KSLICE 4128
#define LDA 40

__device__ __nv_bfloat16 g_Ah[(size_t)BATCH * FLAT];
__device__ __nv_bfloat16 g_Al[(size_t)BATCH * FLAT];
__device__ __nv_bfloat16 g_Wh[(size_t)NQ * FLAT];
__device__ __nv_bfloat16 g_Wl[(size_t)NQ * FLAT];
__device__ float         g_Q[(size_t)KSPLIT * BATCH * NQ];   // 4 partial planes
__device__ float         g_K[(size_t)BATCH * TT * 16];
__device__ float         g_P[(size_t)BATCH * TT * 16];

__device__ __forceinline__ unsigned pack_bf16(float a, float b) {
    unsigned ua = __bfloat16_as_ushort(__float2bfloat16(a));
    unsigned ub = __bfloat16_as_ushort(__float2bfloat16(b));
    return ua | (ub << 16);
}

// ---------- kernel 1: prep (blocks 0..8191) + W hi/lo split (blocks 8192..9215) ----------
__global__ __launch_bounds__(256, 2) void kprep(const float* __restrict__ z_seq,
                                                const float* __restrict__ gamma,
                                                const float* __restrict__ beta,
                                                const float* __restrict__ Wk,
                                                const float* __restrict__ Ws,
                                                const float* __restrict__ Wq1,
                                                const float* __restrict__ Wq2) {
    int tid = threadIdx.x;

    if (blockIdx.x >= BATCH) {
        // -------- W_q1|W_q2 hi/lo split (packed 4-wide: FLAT = 4128*4) --------
        int row = blockIdx.x - BATCH;          // 0..1023
        const float* src = (row < 512) ? (Wq1 + (size_t)row * FLAT)
                                       : (Wq2 + (size_t)(row - 512) * FLAT);
        size_t o = (size_t)row * FLAT;
        for (int i4 = tid; i4 < 4128; i4 += 256) {
            int base = i4 * 4;
            float4 v = *(const float4*)(src + base);
            __nv_bfloat16 h0 = __float2bfloat16(v.x), h1 = __float2bfloat16(v.y);
            __nv_bfloat16 h2 = __float2bfloat16(v.z), h3 = __float2bfloat16(v.w);
            uint2 hp, lp;
            hp.x = (unsigned)__bfloat16_as_ushort(h0) | ((unsigned)__bfloat16_as_ushort(h1) << 16);
            hp.y = (unsigned)__bfloat16_as_ushort(h2) | ((unsigned)__bfloat16_as_ushort(h3) << 16);
            lp.x = pack_bf16(v.x - __bfloat162float(h0), v.y - __bfloat162float(h1));
            lp.y = pack_bf16(v.z - __bfloat162float(h2), v.w - __bfloat162float(h3));
            *(uint2*)(g_Wh + o + base) = hp;
            *(uint2*)(g_Wl + o + base) = lp;
        }
        return;
    }

    extern __shared__ __align__(16) float sp[];
    float* s_zt = sp;             // [128][132]
    float* s_wk = sp + 16896;     // [16][132]
    float* s_ws = sp + 19008;     // [16][132]
    __shared__ float ssum[2][128], ssq[2][128], sS[128], sC[128];

    int b = blockIdx.x;
    const float* zp = z_seq + (size_t)b * TT * 128;

    for (int i = tid; i < 16 * 132; i += 256) {
        int k = i / 132, d = i - k * 132;
        s_wk[i] = (d < 129) ? Wk[k * 129 + d] : 0.f;
        s_ws[i] = (d < 129) ? Ws[k * 129 + d] : 0.f;
    }

    // stats pass: also cache raw z into smem (single HBM read)
    int z = tid & 127, half = tid >> 7;
    float s0 = 0.f, q0 = 0.f;
    int t0 = half * 64;
    for (int t = t0; t < t0 + 64; ++t) {
        float v = zp[t * 128 + z];
        s0 += v; q0 += v * v;
        s_zt[t * 132 + z] = v;
    }
    ssum[half][z] = s0; ssq[half][z] = q0;
    __syncthreads();
    if (tid < 128) {
        float sm = ssum[0][tid] + ssum[1][tid];
        float sq = ssq[0][tid] + ssq[1][tid];
        float mu = sm / 128.0f;
        float var = (sq - 128.0f * mu * mu) / 127.0f;
        float sig = sqrtf(var + 1e-8f);
        float s = gamma[tid] / sig;
        sS[tid] = s;
        sC[tid] = beta[tid] - mu * s;
    }
    __syncthreads();

    // normalize + tag; write zt to smem and hi/lo packed 4-wide to global
    size_t ob = (size_t)b * FLAT;
    for (int i4 = tid; i4 < 4128; i4 += 256) {
        int base = i4 * 4;
        float v[4];
#pragma unroll
        for (int e = 0; e < 4; e++) {
            int idx = base + e;
            int t = idx / ZT, d = idx - t * ZT;
            float x = (d < 128) ? (s_zt[t * 132 + d] * sS[d] + sC[d]) : (float)t;
            v[e] = x;
        }
        __nv_bfloat16 h0 = __float2bfloat16(v[0]), h1 = __float2bfloat16(v[1]);
        __nv_bfloat16 h2 = __float2bfloat16(v[2]), h3 = __float2bfloat16(v[3]);
        uint2 hp, lp;
        hp.x = (unsigned)__bfloat16_as_ushort(h0) | ((unsigned)__bfloat16_as_ushort(h1) << 16);
        hp.y = (unsigned)__bfloat16_as_ushort(h2) | ((unsigned)__bfloat16_as_ushort(h3) << 16);
        lp.x = pack_bf16(v[0] - __bfloat162float(h0), v[1] - __bfloat162float(h1));
        lp.y = pack_bf16(v[2] - __bfloat162float(h2), v[3] - __bfloat162float(h3));
        *(uint2*)(g_Ah + ob + base) = hp;
        *(uint2*)(g_Al + ob + base) = lp;
    }
    __syncthreads();
    // write normalized values (and tag) back into s_zt for the projection
    for (int idx = tid; idx < FLAT; idx += 256) {
        int t = idx / ZT, d = idx - t * ZT;
        if (d < 128) s_zt[t * 132 + d] = s_zt[t * 132 + d] * sS[d] + sC[d];
        else         s_zt[t * 132 + d] = (float)t;
    }
    for (int j = tid; j < 128 * 3; j += 256) {
        int t = j / 3, d = 129 + (j - t * 3);
        s_zt[t * 132 + d] = 0.f;
    }
    __syncthreads();

    {
        int w = tid >> 5, lane = tid & 31;
        int t = (w & 3) * 32 + lane;
        const float4* zrow = (const float4*)(s_zt + t * 132);
        const float4* wb = (const float4*)((w < 4) ? s_wk : s_ws);
        float a[16];
#pragma unroll
        for (int k = 0; k < 16; k++) a[k] = 0.f;
        for (int c = 0; c < 33; c++) {
            float4 zv = zrow[c];
#pragma unroll
            for (int k = 0; k < 16; k++) {
                float4 wv = wb[k * 33 + c];
                a[k] += zv.x * wv.x + zv.y * wv.y + zv.z * wv.z + zv.w * wv.w;
            }
        }
        float4* dst = (float4*)(((w < 4) ? g_K : g_P) + (size_t)b * 2048 + t * 16);
        dst[0] = make_float4(a[0], a[1], a[2], a[3]);
        dst[1] = make_float4(a[4], a[5], a[6], a[7]);
        dst[2] = make_float4(a[8], a[9], a[10], a[11]);
        dst[3] = make_float4(a[12], a[13], a[14], a[15]);
    }
}

// ---------- kernel 2: split-bf16 GEMM, K-split x4, occ 2, 1 sync/kt (R11 exact) ----------
#define CPA(dst, src) asm volatile("cp.async.cg.shared.global [%0], [%1], 16;\n" :: "r"(dst), "l"(src))
#define CPCOMMIT() asm volatile("cp.async.commit_group;\n" ::: "memory")
#define CPWAIT0() asm volatile("cp.async.wait_group 0;\n" ::: "memory")
#define LDM4(R, addr) asm volatile("ldmatrix.sync.aligned.m8n8.x4.shared.b16 {%0,%1,%2,%3},[%4];\n" \
    : "=r"((R)[0]), "=r"((R)[1]), "=r"((R)[2]), "=r"((R)[3]) : "r"(addr))

__device__ __forceinline__ void mma16816(float* c, const unsigned* a, const unsigned* b) {
    asm volatile("mma.sync.aligned.m16n8k16.row.col.f32.bf16.bf16.f32 "
        "{%0,%1,%2,%3},{%4,%5,%6,%7},{%8,%9},{%0,%1,%2,%3};\n"
        : "+f"(c[0]), "+f"(c[1]), "+f"(c[2]), "+f"(c[3])
        : "r"(a[0]), "r"(a[1]), "r"(a[2]), "r"(a[3]), "r"(b[0]), "r"(b[1]));
}

__global__ __launch_bounds__(256, 2) void kgemm() {
    extern __shared__ __align__(16) __nv_bfloat16 smg[];
    unsigned sbase = (unsigned)__cvta_generic_to_shared(smg);
    int tid = threadIdx.x;
    int bx = blockIdx.x;            // 2048 = kh(4) * bm(64) * bn(8), kh-major, bn inner
    int kh = bx >> 9;
    int rem = bx & 511;
    int bm = rem >> 3;
    int bn = rem & 7;
    int ldr = tid >> 2, ldc = (tid & 3) * 8;
    int lane = tid & 31, warp = tid >> 5;
    int m0w = (warp & 1) * 64, n0w = (warp >> 1) * 32;

    size_t kbase = (size_t)kh * KSLICE;
    const __nv_bfloat16* pa0 = g_Ah + (size_t)(bm * 128 + ldr) * FLAT + kbase + ldc;
    const __nv_bfloat16* pl0 = g_Al + (size_t)(bm * 128 + ldr) * FLAT + kbase + ldc;
    const __nv_bfloat16* pb0 = g_Wh + (size_t)(bn * 128 + ldr) * FLAT + kbase + ldc;
    const __nv_bfloat16* pq0 = g_Wl + (size_t)(bn * 128 + ldr) * FLAT + kbase + ldc;
    unsigned s0 = sbase + (unsigned)((ldr * LDA + ldc) * 2);

    float acc[4][4][4];
#pragma unroll
    for (int i = 0; i < 4; i++)
#pragma unroll
        for (int j = 0; j < 4; j++) {
            acc[i][j][0] = 0.f; acc[i][j][1] = 0.f; acc[i][j][2] = 0.f; acc[i][j][3] = 0.f;
        }

    unsigned aoff = sbase + (unsigned)((((m0w + (lane & 15)) * LDA) + (lane >> 4) * 8) * 2);
    unsigned boff = sbase + (unsigned)((((n0w + (lane & 7) + ((lane >> 4) & 1) * 8) * LDA) + ((lane >> 3) & 1) * 8) * 2);

#define ISSUE(buf, kt) do { \
    size_t kk = (size_t)(kt) * 32; \
    unsigned sd = s0 + (unsigned)(buf) * 40960u; \
    CPA(sd,           pa0 + kk); CPA(sd + 5120u,  pa0 + kk + (size_t)64 * FLAT); \
    CPA(sd + 10240u,  pl0 + kk); CPA(sd + 15360u, pl0 + kk + (size_t)64 * FLAT); \
    CPA(sd + 20480u,  pb0 + kk); CPA(sd + 25600u, pb0 + kk + (size_t)64 * FLAT); \
    CPA(sd + 30720u,  pq0 + kk); CPA(sd + 35840u, pq0 + kk + (size_t)64 * FLAT); \
} while (0)

    ISSUE(0, 0);
    CPCOMMIT();

    int buf = 0;
    for (int kt = 0; kt < KT; kt++) {
        CPWAIT0();
        __syncthreads();
        if (kt + 1 < KT) {
            ISSUE(buf ^ 1, kt + 1);
            CPCOMMIT();
        }
        unsigned ab = aoff + (unsigned)buf * 40960u;
        unsigned bb = boff + (unsigned)buf * 40960u;
#pragma unroll
        for (int kf = 0; kf < 2; kf++) {
            unsigned ak = ab + kf * 32u, bk = bb + kf * 32u;
            unsigned aH[4][4], aL[4][4], bH[2][4], bL[2][4];
#pragma unroll
            for (int mi = 0; mi < 4; mi++) LDM4(aH[mi], ak + mi * 1280u);
#pragma unroll
            for (int pi = 0; pi < 2; pi++) LDM4(bH[pi], bk + 20480u + pi * 1280u);
#pragma unroll
            for (int mi = 0; mi < 4; mi++)
#pragma unroll
                for (int ni = 0; ni < 4; ni++)
                    mma16816(acc[mi][ni], aH[mi], &bH[ni >> 1][(ni & 1) * 2]);
#pragma unroll
            for (int mi = 0; mi < 4; mi++) LDM4(aL[mi], ak + 10240u + mi * 1280u);
#pragma unroll
            for (int mi = 0; mi < 4; mi++)
#pragma unroll
                for (int ni = 0; ni < 4; ni++)
                    mma16816(acc[mi][ni], aL[mi], &bH[ni >> 1][(ni & 1) * 2]);
#pragma unroll
            for (int pi = 0; pi < 2; pi++) LDM4(bL[pi], bk + 30720u + pi * 1280u);
#pragma unroll
            for (int mi = 0; mi < 4; mi++)
#pragma unroll
                for (int ni = 0; ni < 4; ni++)
                    mma16816(acc[mi][ni], aH[mi], &bL[ni >> 1][(ni & 1) * 2]);
        }
        buf ^= 1;
    }

    float* plane = g_Q + (size_t)kh * BATCH * NQ;
    int crow = lane >> 2, ccol = (lane & 3) * 2;
#pragma unroll
    for (int mi = 0; mi < 4; mi++)
#pragma unroll
        for (int ni = 0; ni < 4; ni++) {
            int m = bm * 128 + m0w + mi * 16 + crow;
            int n = bn * 128 + n0w + ni * 8 + ccol;
            float* o = plane + (size_t)m * NQ + n;
            o[0] = acc[mi][ni][0]; o[1] = acc[mi][ni][1];
            float* o2 = o + 8 * NQ;
            o2[0] = acc[mi][ni][2]; o2[1] = acc[mi][ni][3];
        }
}

// ---------- kernel 3: scores + softmax + relations + MLP + argmax (R14 exact) ----------
__global__ __launch_bounds__(256, 4) void kattend(
    const float* __restrict__ Wh, const float* __restrict__ bh,
    const float* __restrict__ Wy, const float* __restrict__ by,
    float* __restrict__ out, int out_size) {
    extern __shared__ __align__(16) float sm[];
    float* s_q   = sm;                 // [64][16]
    float* s_k   = sm + 1024;          // [128][17]
    float* s_p   = sm + 3200;          // [128][17]
    float* s_s   = sm + 5376;          // [64][129]
    float* s_tag = sm + 13632;         // [64]
    float* s_r   = sm + 13696;         // [576 + 8]

    int tid = threadIdx.x;
    int b = blockIdx.x;
    int lane = tid & 31, w = tid >> 5;

    const size_t PL = (size_t)BATCH * NQ;
    {
        const float4* q0 = (const float4*)(g_Q + (size_t)b * NQ);
        const float4* q1 = (const float4*)(g_Q + PL + (size_t)b * NQ);
        const float4* q2 = (const float4*)(g_Q + 2 * PL + (size_t)b * NQ);
        const float4* q3 = (const float4*)(g_Q + 3 * PL + (size_t)b * NQ);
        float4 a = q0[tid], bq = q1[tid], c = q2[tid], d = q3[tid];
        float4 r;
        r.x = (a.x + bq.x) + (c.x + d.x);
        r.y = (a.y + bq.y) + (c.y + d.y);
        r.z = (a.z + bq.z) + (c.z + d.z);
        r.w = (a.w + bq.w) + (c.w + d.w);
        ((float4*)s_q)[tid] = r;
    }
    {
        const float4* kg = (const float4*)(g_K + (size_t)b * 2048);
        const float4* pg = (const float4*)(g_P + (size_t)b * 2048);
        for (int i4 = tid; i4 < 512; i4 += 256) {
            int t = i4 >> 2, k0 = (i4 & 3) * 4;
            float4 kv = kg[i4], pv = pg[i4];
            s_k[t * 17 + k0] = kv.x; s_k[t * 17 + k0 + 1] = kv.y;
            s_k[t * 17 + k0 + 2] = kv.z; s_k[t * 17 + k0 + 3] = kv.w;
            s_p[t * 17 + k0] = pv.x; s_p[t * 17 + k0 + 1] = pv.y;
            s_p[t * 17 + k0 + 2] = pv.z; s_p[t * 17 + k0 + 3] = pv.w;
        }
    }
    __syncthreads();

    {
        int t = tid & 127, hb = (tid >> 7) * 32;
        float kr[16];
#pragma unroll
        for (int k = 0; k < 16; k++) kr[k] = s_k[t * 17 + k];
        for (int j = 0; j < 32; j++) {
            int h = hb + j;
            float acc = 0.f;
#pragma unroll
            for (int k = 0; k < 16; k++) acc += kr[k] * s_q[h * 16 + k];
            s_s[h * 129 + t] = acc;
        }
    }
    __syncthreads();

    for (int r = 0; r < 8; r++) {
        int h = w * 8 + r;
        float* row = s_s + h * 129;
        float v0 = row[lane], v1 = row[lane + 32], v2 = row[lane + 64], v3 = row[lane + 96];
        float mx = fmaxf(fmaxf(v0, v1), fmaxf(v2, v3));
#pragma unroll
        for (int d = 16; d > 0; d >>= 1) mx = fmaxf(mx, __shfl_xor_sync(0xffffffffu, mx, d));
        float e0 = __expf(v0 - mx), e1 = __expf(v1 - mx), e2 = __expf(v2 - mx), e3 = __expf(v3 - mx);
        float sum = e0 + e1 + e2 + e3;
#pragma unroll
        for (int d = 16; d > 0; d >>= 1) sum += __shfl_xor_sync(0xffffffffu, sum, d);
        float inv = 1.0f / sum;
        row[lane] = e0 * inv; row[lane + 32] = e1 * inv;
        row[lane + 64] = e2 * inv; row[lane + 96] = e3 * inv;
        float tg = inv * (e0 * (float)lane + e1 * (float)(lane + 32)
                        + e2 * (float)(lane + 64) + e3 * (float)(lane + 96));
#pragma unroll
        for (int d = 16; d > 0; d >>= 1) tg += __shfl_xor_sync(0xffffffffu, tg, d);
        if (lane == 0) s_tag[h] = tg;
    }
    __syncthreads();

    // A1-A2 in place (rows 0..31 of s_s)
    for (int i = tid; i < 32 * 128; i += 256) {
        int h = i >> 7, t = i & 127;
        s_s[h * 129 + t] = s_s[h * 129 + t] - s_s[(h + 32) * 129 + t];
    }
    __syncthreads();

    {
        int h = tid >> 3, rg = tid & 7;
        float a0 = 0.f, a1 = 0.f;
        const float* ad = s_s + h * 129;
        for (int t = 0; t < 128; t++) {
            float a = ad[t];
            a0 += a * s_p[t * 17 + 2 * rg];
            a1 += a * s_p[t * 17 + 2 * rg + 1];
        }
        s_r[h * 18 + 2 * rg] = a0;
        s_r[h * 18 + 2 * rg + 1] = a1;
    }
    if (tid < 32) {
        s_r[tid * 18 + 16] = s_tag[tid];
        s_r[tid * 18 + 17] = s_tag[tid + 32];
    }
    __syncthreads();

    {
        const float* wrow = Wh + w * 576;
        float acc = 0.f;
        for (int j = lane; j < 576; j += 32) acc += wrow[j] * s_r[j];
#pragma unroll
        for (int d = 16; d > 0; d >>= 1) acc += __shfl_xor_sync(0xffffffffu, acc, d);
        if (lane == 0) s_r[576 + w] = fmaxf(acc + bh[w], 0.f);
    }
    __syncthreads();

    if (tid == 0) {
        float y[4];
#pragma unroll
        for (int c = 0; c < 4; c++) {
            float acc = by[c];
#pragma unroll
            for (int i = 0; i < 8; i++) acc += Wy[c * 8 + i] * s_r[576 + i];
            y[c] = acc;
        }
        int amax = 0;
#pragma unroll
        for (int c = 1; c < 4; c++) if (y[c] > y[amax]) amax = c;
        if (out_size >= 5 * BATCH) {
            for (int c = 0; c < 4; c++) out[b * 4 + c] = y[c];
            out[4 * BATCH + b] = (float)amax;
        } else if (out_size >= 4 * BATCH) {
            for (int c = 0; c < 4; c++) out[b * 4 + c] = y[c];
        } else if (out_size >= BATCH) {
            out[b] = (float)amax;
        }
    }
}

extern "C" void kernel_launch(void* const* d_in, const int* in_sizes, int n_in,
                              void* d_out, int out_size) {
    const float* z_seq = (const float*)d_in[0];
    const float* W_k   = (const float*)d_in[1];
    const float* W_q1  = (const float*)d_in[2];
    const float* W_q2  = (const float*)d_in[3];
    const float* W_s   = (const float*)d_in[4];
    const float* gamma = (const float*)d_in[5];
    const float* beta  = (const float*)d_in[6];
    const float* W_h   = (const float*)d_in[7];
    const float* b_h   = (const float*)d_in[8];
    const float* W_y   = (const float*)d_in[9];
    const float* b_y   = (const float*)d_in[10];
    float* out = (float*)d_out;

    cudaFuncSetAttribute(kprep,   cudaFuncAttributeMaxDynamicSharedMemorySize, 84480);
    cudaFuncSetAttribute(kgemm,   cudaFuncAttributeMaxDynamicSharedMemorySize, 81920);
    cudaFuncSetAttribute(kattend, cudaFuncAttributeMaxDynamicSharedMemorySize, 57152);

    kprep<<<BATCH + 1024, 256, 84480>>>(z_seq, gamma, beta, W_k, W_s, W_q1, W_q2);
    kgemm<<<2048, 256, 81920>>>();
    kattend<<<8192, 256, 57152>>>(W_h, b_h, W_y, b_y, out, out_size);
}

// round 16
// speedup vs baseline: 1.0271x; 1.0271x over previous
#include <cuda_runtime.h>
#include <cuda_bf16.h>

#define BATCH 8192
#define TT 128
#define ZT 129
#define FLAT 16512
#define NQ 1024
#define KT 129          // per K-split: 4128 = 129*32
#define KSPLIT 4
#define KSLICE 4128
#define LDA 40

__device__ __nv_bfloat16 g_Ah[(size_t)BATCH * FLAT];
__device__ __nv_bfloat16 g_Al[(size_t)BATCH * FLAT];
__device__ __nv_bfloat16 g_Wh[(size_t)NQ * FLAT];
__device__ __nv_bfloat16 g_Wl[(size_t)NQ * FLAT];
__device__ float         g_Q[(size_t)KSPLIT * BATCH * NQ];   // 4 partial planes
__device__ float         g_K[(size_t)BATCH * TT * 16];
__device__ float         g_P[(size_t)BATCH * TT * 16];

// ---------- kernel 1: prep (blocks 0..8191) + W hi/lo split (blocks 8192..9215) ----------
__global__ __launch_bounds__(256, 3) void kprep(const float* __restrict__ z_seq,
                                                const float* __restrict__ gamma,
                                                const float* __restrict__ beta,
                                                const float* __restrict__ Wk,
                                                const float* __restrict__ Ws,
                                                const float* __restrict__ Wq1,
                                                const float* __restrict__ Wq2) {
    int tid = threadIdx.x;

    if (blockIdx.x >= BATCH) {
        // -------- W_q1|W_q2 hi/lo split (R13-proven scalar form) --------
        int row = blockIdx.x - BATCH;          // 0..1023
        const float* src = (row < 512) ? (Wq1 + (size_t)row * FLAT)
                                       : (Wq2 + (size_t)(row - 512) * FLAT);
        size_t o = (size_t)row * FLAT;
        for (int k = tid; k < FLAT; k += 256) {
            float v = src[k];
            __nv_bfloat16 h = __float2bfloat16(v);
            g_Wh[o + k] = h;
            g_Wl[o + k] = __float2bfloat16(v - __bfloat162float(h));
        }
        return;
    }

    __shared__ float s_wk[16 * 132], s_ws[16 * 132];   // sS-scaled weights [k][d]
    __shared__ float ssum[2][128], ssq[2][128], sS[128], sC[128];
    __shared__ float sbk[16], sbs[16];                  // bias terms sum_d sC[d]*W[k,d]

    int b = blockIdx.x;
    const float* zp = z_seq + (size_t)b * TT * 128;

    // phase 1: stats (single streaming read of z; stays L2-hot for later phases)
    int z = tid & 127, half = tid >> 7;
    float s0 = 0.f, q0 = 0.f;
    int t0 = half * 64;
    for (int t = t0; t < t0 + 64; ++t) {
        float v = zp[t * 128 + z];
        s0 += v; q0 += v * v;
    }
    ssum[half][z] = s0; ssq[half][z] = q0;
    __syncthreads();
    if (tid < 128) {
        float sm = ssum[0][tid] + ssum[1][tid];
        float sq = ssq[0][tid] + ssq[1][tid];
        float mu = sm / 128.0f;
        float var = (sq - 128.0f * mu * mu) / 127.0f;
        float sig = sqrtf(var + 1e-8f);
        float s = gamma[tid] / sig;
        sS[tid] = s;
        sC[tid] = beta[tid] - mu * s;
    }
    __syncthreads();

    // phase 2: scaled weights (d<128 scaled by sS; d=128 tag col unscaled; pad 0)
    for (int i = tid; i < 16 * 132; i += 256) {
        int k = i / 132, d = i - k * 132;
        float wk = (d < 129) ? Wk[k * 129 + d] : 0.f;
        float ws = (d < 129) ? Ws[k * 129 + d] : 0.f;
        float sc = (d < 128) ? sS[d] : 1.0f;
        s_wk[i] = wk * sc;
        s_ws[i] = ws * sc;
    }
    // bias terms (32 threads, serial 128-sums; L1-hot weight reads)
    if (tid < 32) {
        int k = tid & 15;
        const float* W = (tid < 16) ? Wk : Ws;
        float acc = 0.f;
        for (int d = 0; d < 128; d++) acc += sC[d] * W[k * 129 + d];
        if (tid < 16) sbk[k] = acc; else sbs[k] = acc;
    }
    __syncthreads();

    // phase 3: projection — raw z from global (L2-hot) vs scaled smem weights
    {
        int w = tid >> 5, lane = tid & 31;
        int t = (w & 3) * 32 + lane;
        const float4* zrow = (const float4*)(zp + t * 128);   // 32 float4
        const float4* wb = (const float4*)((w < 4) ? s_wk : s_ws);
        const float* bias = (w < 4) ? sbk : sbs;
        float a[16];
#pragma unroll
        for (int k = 0; k < 16; k++) a[k] = bias[k];
        for (int c = 0; c < 32; c++) {
            float4 zv = zrow[c];
#pragma unroll
            for (int k = 0; k < 16; k++) {
                float4 wv = wb[k * 33 + c];
                a[k] += zv.x * wv.x + zv.y * wv.y + zv.z * wv.z + zv.w * wv.w;
            }
        }
        float tf = (float)t;
#pragma unroll
        for (int k = 0; k < 16; k++) a[k] += tf * wb[k * 33 + 32].x;   // tag col d=128
        float4* dst = (float4*)(((w < 4) ? g_K : g_P) + (size_t)b * 2048 + t * 16);
        dst[0] = make_float4(a[0], a[1], a[2], a[3]);
        dst[1] = make_float4(a[4], a[5], a[6], a[7]);
        dst[2] = make_float4(a[8], a[9], a[10], a[11]);
        dst[3] = make_float4(a[12], a[13], a[14], a[15]);
    }

    // phase 4: normalize + tag + hi/lo split (z re-read from L2; R13-proven form)
    size_t ob = (size_t)b * FLAT;
    for (int idx = tid; idx < FLAT; idx += 256) {
        int t = idx / ZT, d = idx - t * ZT;
        float v = (d < 128) ? (zp[t * 128 + d] * sS[d] + sC[d]) : (float)t;
        __nv_bfloat16 h = __float2bfloat16(v);
        g_Ah[ob + idx] = h;
        g_Al[ob + idx] = __float2bfloat16(v - __bfloat162float(h));
    }
}

// ---------- kernel 2: split-bf16 GEMM, K-split x4, occ 2, 1 sync/kt (R11 exact) ----------
#define CPA(dst, src) asm volatile("cp.async.cg.shared.global [%0], [%1], 16;\n" :: "r"(dst), "l"(src))
#define CPCOMMIT() asm volatile("cp.async.commit_group;\n" ::: "memory")
#define CPWAIT0() asm volatile("cp.async.wait_group 0;\n" ::: "memory")
#define LDM4(R, addr) asm volatile("ldmatrix.sync.aligned.m8n8.x4.shared.b16 {%0,%1,%2,%3},[%4];\n" \
    : "=r"((R)[0]), "=r"((R)[1]), "=r"((R)[2]), "=r"((R)[3]) : "r"(addr))

__device__ __forceinline__ void mma16816(float* c, const unsigned* a, const unsigned* b) {
    asm volatile("mma.sync.aligned.m16n8k16.row.col.f32.bf16.bf16.f32 "
        "{%0,%1,%2,%3},{%4,%5,%6,%7},{%8,%9},{%0,%1,%2,%3};\n"
        : "+f"(c[0]), "+f"(c[1]), "+f"(c[2]), "+f"(c[3])
        : "r"(a[0]), "r"(a[1]), "r"(a[2]), "r"(a[3]), "r"(b[0]), "r"(b[1]));
}

__global__ __launch_bounds__(256, 2) void kgemm() {
    extern __shared__ __align__(16) __nv_bfloat16 smg[];
    unsigned sbase = (unsigned)__cvta_generic_to_shared(smg);
    int tid = threadIdx.x;
    int bx = blockIdx.x;            // 2048 = kh(4) * bm(64) * bn(8), kh-major, bn inner
    int kh = bx >> 9;
    int rem = bx & 511;
    int bm = rem >> 3;
    int bn = rem & 7;
    int ldr = tid >> 2, ldc = (tid & 3) * 8;
    int lane = tid & 31, warp = tid >> 5;
    int m0w = (warp & 1) * 64, n0w = (warp >> 1) * 32;

    size_t kbase = (size_t)kh * KSLICE;
    const __nv_bfloat16* pa0 = g_Ah + (size_t)(bm * 128 + ldr) * FLAT + kbase + ldc;
    const __nv_bfloat16* pl0 = g_Al + (size_t)(bm * 128 + ldr) * FLAT + kbase + ldc;
    const __nv_bfloat16* pb0 = g_Wh + (size_t)(bn * 128 + ldr) * FLAT + kbase + ldc;
    const __nv_bfloat16* pq0 = g_Wl + (size_t)(bn * 128 + ldr) * FLAT + kbase + ldc;
    unsigned s0 = sbase + (unsigned)((ldr * LDA + ldc) * 2);

    float acc[4][4][4];
#pragma unroll
    for (int i = 0; i < 4; i++)
#pragma unroll
        for (int j = 0; j < 4; j++) {
            acc[i][j][0] = 0.f; acc[i][j][1] = 0.f; acc[i][j][2] = 0.f; acc[i][j][3] = 0.f;
        }

    unsigned aoff = sbase + (unsigned)((((m0w + (lane & 15)) * LDA) + (lane >> 4) * 8) * 2);
    unsigned boff = sbase + (unsigned)((((n0w + (lane & 7) + ((lane >> 4) & 1) * 8) * LDA) + ((lane >> 3) & 1) * 8) * 2);

#define ISSUE(buf, kt) do { \
    size_t kk = (size_t)(kt) * 32; \
    unsigned sd = s0 + (unsigned)(buf) * 40960u; \
    CPA(sd,           pa0 + kk); CPA(sd + 5120u,  pa0 + kk + (size_t)64 * FLAT); \
    CPA(sd + 10240u,  pl0 + kk); CPA(sd + 15360u, pl0 + kk + (size_t)64 * FLAT); \
    CPA(sd + 20480u,  pb0 + kk); CPA(sd + 25600u, pb0 + kk + (size_t)64 * FLAT); \
    CPA(sd + 30720u,  pq0 + kk); CPA(sd + 35840u, pq0 + kk + (size_t)64 * FLAT); \
} while (0)

    ISSUE(0, 0);
    CPCOMMIT();

    int buf = 0;
    for (int kt = 0; kt < KT; kt++) {
        CPWAIT0();
        __syncthreads();
        if (kt + 1 < KT) {
            ISSUE(buf ^ 1, kt + 1);
            CPCOMMIT();
        }
        unsigned ab = aoff + (unsigned)buf * 40960u;
        unsigned bb = boff + (unsigned)buf * 40960u;
#pragma unroll
        for (int kf = 0; kf < 2; kf++) {
            unsigned ak = ab + kf * 32u, bk = bb + kf * 32u;
            unsigned aH[4][4], aL[4][4], bH[2][4], bL[2][4];
#pragma unroll
            for (int mi = 0; mi < 4; mi++) LDM4(aH[mi], ak + mi * 1280u);
#pragma unroll
            for (int pi = 0; pi < 2; pi++) LDM4(bH[pi], bk + 20480u + pi * 1280u);
#pragma unroll
            for (int mi = 0; mi < 4; mi++)
#pragma unroll
                for (int ni = 0; ni < 4; ni++)
                    mma16816(acc[mi][ni], aH[mi], &bH[ni >> 1][(ni & 1) * 2]);
#pragma unroll
            for (int mi = 0; mi < 4; mi++) LDM4(aL[mi], ak + 10240u + mi * 1280u);
#pragma unroll
            for (int mi = 0; mi < 4; mi++)
#pragma unroll
                for (int ni = 0; ni < 4; ni++)
                    mma16816(acc[mi][ni], aL[mi], &bH[ni >> 1][(ni & 1) * 2]);
#pragma unroll
            for (int pi = 0; pi < 2; pi++) LDM4(bL[pi], bk + 30720u + pi * 1280u);
#pragma unroll
            for (int mi = 0; mi < 4; mi++)
#pragma unroll
                for (int ni = 0; ni < 4; ni++)
                    mma16816(acc[mi][ni], aH[mi], &bL[ni >> 1][(ni & 1) * 2]);
        }
        buf ^= 1;
    }

    float* plane = g_Q + (size_t)kh * BATCH * NQ;
    int crow = lane >> 2, ccol = (lane & 3) * 2;
#pragma unroll
    for (int mi = 0; mi < 4; mi++)
#pragma unroll
        for (int ni = 0; ni < 4; ni++) {
            int m = bm * 128 + m0w + mi * 16 + crow;
            int n = bn * 128 + n0w + ni * 8 + ccol;
            float* o = plane + (size_t)m * NQ + n;
            o[0] = acc[mi][ni][0]; o[1] = acc[mi][ni][1];
            float* o2 = o + 8 * NQ;
            o2[0] = acc[mi][ni][2]; o2[1] = acc[mi][ni][3];
        }
}

// ---------- kernel 3: scores + softmax + relations + MLP + argmax (R14 exact) ----------
__global__ __launch_bounds__(256, 4) void kattend(
    const float* __restrict__ Wh, const float* __restrict__ bh,
    const float* __restrict__ Wy, const float* __restrict__ by,
    float* __restrict__ out, int out_size) {
    extern __shared__ __align__(16) float sm[];
    float* s_q   = sm;                 // [64][16]
    float* s_k   = sm + 1024;          // [128][17]
    float* s_p   = sm + 3200;          // [128][17]
    float* s_s   = sm + 5376;          // [64][129]
    float* s_tag = sm + 13632;         // [64]
    float* s_r   = sm + 13696;         // [576 + 8]

    int tid = threadIdx.x;
    int b = blockIdx.x;
    int lane = tid & 31, w = tid >> 5;

    const size_t PL = (size_t)BATCH * NQ;
    {
        const float4* q0 = (const float4*)(g_Q + (size_t)b * NQ);
        const float4* q1 = (const float4*)(g_Q + PL + (size_t)b * NQ);
        const float4* q2 = (const float4*)(g_Q + 2 * PL + (size_t)b * NQ);
        const float4* q3 = (const float4*)(g_Q + 3 * PL + (size_t)b * NQ);
        float4 a = q0[tid], bq = q1[tid], c = q2[tid], d = q3[tid];
        float4 r;
        r.x = (a.x + bq.x) + (c.x + d.x);
        r.y = (a.y + bq.y) + (c.y + d.y);
        r.z = (a.z + bq.z) + (c.z + d.z);
        r.w = (a.w + bq.w) + (c.w + d.w);
        ((float4*)s_q)[tid] = r;
    }
    {
        const float4* kg = (const float4*)(g_K + (size_t)b * 2048);
        const float4* pg = (const float4*)(g_P + (size_t)b * 2048);
        for (int i4 = tid; i4 < 512; i4 += 256) {
            int t = i4 >> 2, k0 = (i4 & 3) * 4;
            float4 kv = kg[i4], pv = pg[i4];
            s_k[t * 17 + k0] = kv.x; s_k[t * 17 + k0 + 1] = kv.y;
            s_k[t * 17 + k0 + 2] = kv.z; s_k[t * 17 + k0 + 3] = kv.w;
            s_p[t * 17 + k0] = pv.x; s_p[t * 17 + k0 + 1] = pv.y;
            s_p[t * 17 + k0 + 2] = pv.z; s_p[t * 17 + k0 + 3] = pv.w;
        }
    }
    __syncthreads();

    {
        int t = tid & 127, hb = (tid >> 7) * 32;
        float kr[16];
#pragma unroll
        for (int k = 0; k < 16; k++) kr[k] = s_k[t * 17 + k];
        for (int j = 0; j < 32; j++) {
            int h = hb + j;
            float acc = 0.f;
#pragma unroll
            for (int k = 0; k < 16; k++) acc += kr[k] * s_q[h * 16 + k];
            s_s[h * 129 + t] = acc;
        }
    }
    __syncthreads();

    for (int r = 0; r < 8; r++) {
        int h = w * 8 + r;
        float* row = s_s + h * 129;
        float v0 = row[lane], v1 = row[lane + 32], v2 = row[lane + 64], v3 = row[lane + 96];
        float mx = fmaxf(fmaxf(v0, v1), fmaxf(v2, v3));
#pragma unroll
        for (int d = 16; d > 0; d >>= 1) mx = fmaxf(mx, __shfl_xor_sync(0xffffffffu, mx, d));
        float e0 = __expf(v0 - mx), e1 = __expf(v1 - mx), e2 = __expf(v2 - mx), e3 = __expf(v3 - mx);
        float sum = e0 + e1 + e2 + e3;
#pragma unroll
        for (int d = 16; d > 0; d >>= 1) sum += __shfl_xor_sync(0xffffffffu, sum, d);
        float inv = 1.0f / sum;
        row[lane] = e0 * inv; row[lane + 32] = e1 * inv;
        row[lane + 64] = e2 * inv; row[lane + 96] = e3 * inv;
        float tg = inv * (e0 * (float)lane + e1 * (float)(lane + 32)
                        + e2 * (float)(lane + 64) + e3 * (float)(lane + 96));
#pragma unroll
        for (int d = 16; d > 0; d >>= 1) tg += __shfl_xor_sync(0xffffffffu, tg, d);
        if (lane == 0) s_tag[h] = tg;
    }
    __syncthreads();

    // A1-A2 in place (rows 0..31 of s_s)
    for (int i = tid; i < 32 * 128; i += 256) {
        int h = i >> 7, t = i & 127;
        s_s[h * 129 + t] = s_s[h * 129 + t] - s_s[(h + 32) * 129 + t];
    }
    __syncthreads();

    {
        int h = tid >> 3, rg = tid & 7;
        float a0 = 0.f, a1 = 0.f;
        const float* ad = s_s + h * 129;
        for (int t = 0; t < 128; t++) {
            float a = ad[t];
            a0 += a * s_p[t * 17 + 2 * rg];
            a1 += a * s_p[t * 17 + 2 * rg + 1];
        }
        s_r[h * 18 + 2 * rg] = a0;
        s_r[h * 18 + 2 * rg + 1] = a1;
    }
    if (tid < 32) {
        s_r[tid * 18 + 16] = s_tag[tid];
        s_r[tid * 18 + 17] = s_tag[tid + 32];
    }
    __syncthreads();

    {
        const float* wrow = Wh + w * 576;
        float acc = 0.f;
        for (int j = lane; j < 576; j += 32) acc += wrow[j] * s_r[j];
#pragma unroll
        for (int d = 16; d > 0; d >>= 1) acc += __shfl_xor_sync(0xffffffffu, acc, d);
        if (lane == 0) s_r[576 + w] = fmaxf(acc + bh[w], 0.f);
    }
    __syncthreads();

    if (tid == 0) {
        float y[4];
#pragma unroll
        for (int c = 0; c < 4; c++) {
            float acc = by[c];
#pragma unroll
            for (int i = 0; i < 8; i++) acc += Wy[c * 8 + i] * s_r[576 + i];
            y[c] = acc;
        }
        int amax = 0;
#pragma unroll
        for (int c = 1; c < 4; c++) if (y[c] > y[amax]) amax = c;
        if (out_size >= 5 * BATCH) {
            for (int c = 0; c < 4; c++) out[b * 4 + c] = y[c];
            out[4 * BATCH + b] = (float)amax;
        } else if (out_size >= 4 * BATCH) {
            for (int c = 0; c < 4; c++) out[b * 4 + c] = y[c];
        } else if (out_size >= BATCH) {
            out[b] = (float)amax;
        }
    }
}

extern "C" void kernel_launch(void* const* d_in, const int* in_sizes, int n_in,
                              void* d_out, int out_size) {
    const float* z_seq = (const float*)d_in[0];
    const float* W_k   = (const float*)d_in[1];
    const float* W_q1  = (const float*)d_in[2];
    const float* W_q2  = (const float*)d_in[3];
    const float* W_s   = (const float*)d_in[4];
    const float* gamma = (const float*)d_in[5];
    const float* beta  = (const float*)d_in[6];
    const float* W_h   = (const float*)d_in[7];
    const float* b_h   = (const float*)d_in[8];
    const float* W_y   = (const float*)d_in[9];
    const float* b_y   = (const float*)d_in[10];
    float* out = (float*)d_out;

    cudaFuncSetAttribute(kgemm,   cudaFuncAttributeMaxDynamicSharedMemorySize, 81920);
    cudaFuncSetAttribute(kattend, cudaFuncAttributeMaxDynamicSharedMemorySize, 57152);

    kprep<<<BATCH + 1024, 256>>>(z_seq, gamma, beta, W_k, W_s, W_q1, W_q2);
    kgemm<<<2048, 256, 81920>>>();
    kattend<<<8192, 256, 57152>>>(W_h, b_h, W_y, b_y, out, out_size);
}

// round 17
// speedup vs baseline: 1.0472x; 1.0196x over previous
#include <cuda_runtime.h>
#include <cuda_bf16.h>

#define BATCH 8192
#define TT 128
#define ZT 129
#define FLAT 16512
#define NQ 1024
#define KT 129          // per K-split: 4128 = 129*32
#define KSPLIT 4
#define KSLICE 4128
#define LDA 40

__device__ __nv_bfloat16 g_Ah[(size_t)BATCH * FLAT];
__device__ __nv_bfloat16 g_Al[(size_t)BATCH * FLAT];
__device__ __nv_bfloat16 g_Wh[(size_t)NQ * FLAT];
__device__ __nv_bfloat16 g_Wl[(size_t)NQ * FLAT];
__device__ float         g_Q[(size_t)KSPLIT * BATCH * NQ];   // 4 partial planes
__device__ float         g_K[(size_t)BATCH * TT * 16];
__device__ float         g_P[(size_t)BATCH * TT * 16];

// ---------- kernel 1: prep (blocks 0..8191) + W hi/lo split (blocks 8192..9215) — R13 exact ----------
__global__ __launch_bounds__(256, 2) void kprep(const float* __restrict__ z_seq,
                                                const float* __restrict__ gamma,
                                                const float* __restrict__ beta,
                                                const float* __restrict__ Wk,
                                                const float* __restrict__ Ws,
                                                const float* __restrict__ Wq1,
                                                const float* __restrict__ Wq2) {
    int tid = threadIdx.x;

    if (blockIdx.x >= BATCH) {
        int row = blockIdx.x - BATCH;          // 0..1023
        const float* src = (row < 512) ? (Wq1 + (size_t)row * FLAT)
                                       : (Wq2 + (size_t)(row - 512) * FLAT);
        size_t o = (size_t)row * FLAT;
        for (int k = tid; k < FLAT; k += 256) {
            float v = src[k];
            __nv_bfloat16 h = __float2bfloat16(v);
            g_Wh[o + k] = h;
            g_Wl[o + k] = __float2bfloat16(v - __bfloat162float(h));
        }
        return;
    }

    extern __shared__ __align__(16) float sp[];
    float* s_zt = sp;             // [128][132]
    float* s_wk = sp + 16896;     // [16][132]
    float* s_ws = sp + 19008;     // [16][132]
    __shared__ float ssum[2][128], ssq[2][128], sS[128], sC[128];

    int b = blockIdx.x;
    const float* zp = z_seq + (size_t)b * TT * 128;

    for (int i = tid; i < 16 * 132; i += 256) {
        int k = i / 132, d = i - k * 132;
        s_wk[i] = (d < 129) ? Wk[k * 129 + d] : 0.f;
        s_ws[i] = (d < 129) ? Ws[k * 129 + d] : 0.f;
    }

    // stats pass: also cache raw z into smem (single HBM read)
    int z = tid & 127, half = tid >> 7;
    float s0 = 0.f, q0 = 0.f;
    int t0 = half * 64;
    for (int t = t0; t < t0 + 64; ++t) {
        float v = zp[t * 128 + z];
        s0 += v; q0 += v * v;
        s_zt[t * 132 + z] = v;
    }
    ssum[half][z] = s0; ssq[half][z] = q0;
    __syncthreads();
    if (tid < 128) {
        float sm = ssum[0][tid] + ssum[1][tid];
        float sq = ssq[0][tid] + ssq[1][tid];
        float mu = sm / 128.0f;
        float var = (sq - 128.0f * mu * mu) / 127.0f;
        float sig = sqrtf(var + 1e-8f);
        float s = gamma[tid] / sig;
        sS[tid] = s;
        sC[tid] = beta[tid] - mu * s;
    }
    __syncthreads();

    size_t ob = (size_t)b * FLAT;
    for (int idx = tid; idx < FLAT; idx += 256) {
        int t = idx / ZT, d = idx - t * ZT;
        float v = (d < 128) ? (s_zt[t * 132 + d] * sS[d] + sC[d]) : (float)t;
        s_zt[t * 132 + d] = v;
        __nv_bfloat16 h = __float2bfloat16(v);
        g_Ah[ob + idx] = h;
        g_Al[ob + idx] = __float2bfloat16(v - __bfloat162float(h));
    }
    for (int j = tid; j < 128 * 3; j += 256) {
        int t = j / 3, d = 129 + (j - t * 3);
        s_zt[t * 132 + d] = 0.f;
    }
    __syncthreads();

    {
        int w = tid >> 5, lane = tid & 31;
        int t = (w & 3) * 32 + lane;
        const float4* zrow = (const float4*)(s_zt + t * 132);
        const float4* wb = (const float4*)((w < 4) ? s_wk : s_ws);
        float a[16];
#pragma unroll
        for (int k = 0; k < 16; k++) a[k] = 0.f;
        for (int c = 0; c < 33; c++) {
            float4 zv = zrow[c];
#pragma unroll
            for (int k = 0; k < 16; k++) {
                float4 wv = wb[k * 33 + c];
                a[k] += zv.x * wv.x + zv.y * wv.y + zv.z * wv.z + zv.w * wv.w;
            }
        }
        float4* dst = (float4*)(((w < 4) ? g_K : g_P) + (size_t)b * 2048 + t * 16);
        dst[0] = make_float4(a[0], a[1], a[2], a[3]);
        dst[1] = make_float4(a[4], a[5], a[6], a[7]);
        dst[2] = make_float4(a[8], a[9], a[10], a[11]);
        dst[3] = make_float4(a[12], a[13], a[14], a[15]);
    }
}

// ---------- kernel 2: split-bf16 GEMM, K-split x4, occ 2, 1 sync/kt (R11 exact) ----------
#define CPA(dst, src) asm volatile("cp.async.cg.shared.global [%0], [%1], 16;\n" :: "r"(dst), "l"(src))
#define CPCOMMIT() asm volatile("cp.async.commit_group;\n" ::: "memory")
#define CPWAIT0() asm volatile("cp.async.wait_group 0;\n" ::: "memory")
#define LDM4(R, addr) asm volatile("ldmatrix.sync.aligned.m8n8.x4.shared.b16 {%0,%1,%2,%3},[%4];\n" \
    : "=r"((R)[0]), "=r"((R)[1]), "=r"((R)[2]), "=r"((R)[3]) : "r"(addr))

__device__ __forceinline__ void mma16816(float* c, const unsigned* a, const unsigned* b) {
    asm volatile("mma.sync.aligned.m16n8k16.row.col.f32.bf16.bf16.f32 "
        "{%0,%1,%2,%3},{%4,%5,%6,%7},{%8,%9},{%0,%1,%2,%3};\n"
        : "+f"(c[0]), "+f"(c[1]), "+f"(c[2]), "+f"(c[3])
        : "r"(a[0]), "r"(a[1]), "r"(a[2]), "r"(a[3]), "r"(b[0]), "r"(b[1]));
}

__global__ __launch_bounds__(256, 2) void kgemm() {
    extern __shared__ __align__(16) __nv_bfloat16 smg[];
    unsigned sbase = (unsigned)__cvta_generic_to_shared(smg);
    int tid = threadIdx.x;
    int bx = blockIdx.x;            // 2048 = kh(4) * bm(64) * bn(8), kh-major, bn inner
    int kh = bx >> 9;
    int rem = bx & 511;
    int bm = rem >> 3;
    int bn = rem & 7;
    int ldr = tid >> 2, ldc = (tid & 3) * 8;
    int lane = tid & 31, warp = tid >> 5;
    int m0w = (warp & 1) * 64, n0w = (warp >> 1) * 32;

    size_t kbase = (size_t)kh * KSLICE;
    const __nv_bfloat16* pa0 = g_Ah + (size_t)(bm * 128 + ldr) * FLAT + kbase + ldc;
    const __nv_bfloat16* pl0 = g_Al + (size_t)(bm * 128 + ldr) * FLAT + kbase + ldc;
    const __nv_bfloat16* pb0 = g_Wh + (size_t)(bn * 128 + ldr) * FLAT + kbase + ldc;
    const __nv_bfloat16* pq0 = g_Wl + (size_t)(bn * 128 + ldr) * FLAT + kbase + ldc;
    unsigned s0 = sbase + (unsigned)((ldr * LDA + ldc) * 2);

    float acc[4][4][4];
#pragma unroll
    for (int i = 0; i < 4; i++)
#pragma unroll
        for (int j = 0; j < 4; j++) {
            acc[i][j][0] = 0.f; acc[i][j][1] = 0.f; acc[i][j][2] = 0.f; acc[i][j][3] = 0.f;
        }

    unsigned aoff = sbase + (unsigned)((((m0w + (lane & 15)) * LDA) + (lane >> 4) * 8) * 2);
    unsigned boff = sbase + (unsigned)((((n0w + (lane & 7) + ((lane >> 4) & 1) * 8) * LDA) + ((lane >> 3) & 1) * 8) * 2);

#define ISSUE(buf, kt) do { \
    size_t kk = (size_t)(kt) * 32; \
    unsigned sd = s0 + (unsigned)(buf) * 40960u; \
    CPA(sd,           pa0 + kk); CPA(sd + 5120u,  pa0 + kk + (size_t)64 * FLAT); \
    CPA(sd + 10240u,  pl0 + kk); CPA(sd + 15360u, pl0 + kk + (size_t)64 * FLAT); \
    CPA(sd + 20480u,  pb0 + kk); CPA(sd + 25600u, pb0 + kk + (size_t)64 * FLAT); \
    CPA(sd + 30720u,  pq0 + kk); CPA(sd + 35840u, pq0 + kk + (size_t)64 * FLAT); \
} while (0)

    ISSUE(0, 0);
    CPCOMMIT();

    int buf = 0;
    for (int kt = 0; kt < KT; kt++) {
        CPWAIT0();
        __syncthreads();
        if (kt + 1 < KT) {
            ISSUE(buf ^ 1, kt + 1);
            CPCOMMIT();
        }
        unsigned ab = aoff + (unsigned)buf * 40960u;
        unsigned bb = boff + (unsigned)buf * 40960u;
#pragma unroll
        for (int kf = 0; kf < 2; kf++) {
            unsigned ak = ab + kf * 32u, bk = bb + kf * 32u;
            unsigned aH[4][4], aL[4][4], bH[2][4], bL[2][4];
#pragma unroll
            for (int mi = 0; mi < 4; mi++) LDM4(aH[mi], ak + mi * 1280u);
#pragma unroll
            for (int pi = 0; pi < 2; pi++) LDM4(bH[pi], bk + 20480u + pi * 1280u);
#pragma unroll
            for (int mi = 0; mi < 4; mi++)
#pragma unroll
                for (int ni = 0; ni < 4; ni++)
                    mma16816(acc[mi][ni], aH[mi], &bH[ni >> 1][(ni & 1) * 2]);
#pragma unroll
            for (int mi = 0; mi < 4; mi++) LDM4(aL[mi], ak + 10240u + mi * 1280u);
#pragma unroll
            for (int mi = 0; mi < 4; mi++)
#pragma unroll
                for (int ni = 0; ni < 4; ni++)
                    mma16816(acc[mi][ni], aL[mi], &bH[ni >> 1][(ni & 1) * 2]);
#pragma unroll
            for (int pi = 0; pi < 2; pi++) LDM4(bL[pi], bk + 30720u + pi * 1280u);
#pragma unroll
            for (int mi = 0; mi < 4; mi++)
#pragma unroll
                for (int ni = 0; ni < 4; ni++)
                    mma16816(acc[mi][ni], aH[mi], &bL[ni >> 1][(ni & 1) * 2]);
        }
        buf ^= 1;
    }

    float* plane = g_Q + (size_t)kh * BATCH * NQ;
    int crow = lane >> 2, ccol = (lane & 3) * 2;
#pragma unroll
    for (int mi = 0; mi < 4; mi++)
#pragma unroll
        for (int ni = 0; ni < 4; ni++) {
            int m = bm * 128 + m0w + mi * 16 + crow;
            int n = bn * 128 + n0w + ni * 8 + ccol;
            float* o = plane + (size_t)m * NQ + n;
            o[0] = acc[mi][ni][0]; o[1] = acc[mi][ni][1];
            float* o2 = o + 8 * NQ;
            o2[0] = acc[mi][ni][2]; o2[1] = acc[mi][ni][3];
        }
}

// ---------- kernel 3: scores + softmax + relations + MLP + argmax (R14 exact) ----------
__global__ __launch_bounds__(256, 4) void kattend(
    const float* __restrict__ Wh, const float* __restrict__ bh,
    const float* __restrict__ Wy, const float* __restrict__ by,
    float* __restrict__ out, int out_size) {
    extern __shared__ __align__(16) float sm[];
    float* s_q   = sm;                 // [64][16]
    float* s_k   = sm + 1024;          // [128][17]
    float* s_p   = sm + 3200;          // [128][17]
    float* s_s   = sm + 5376;          // [64][129]
    float* s_tag = sm + 13632;         // [64]
    float* s_r   = sm + 13696;         // [576 + 8]

    int tid = threadIdx.x;
    int b = blockIdx.x;
    int lane = tid & 31, w = tid >> 5;

    const size_t PL = (size_t)BATCH * NQ;
    {
        const float4* q0 = (const float4*)(g_Q + (size_t)b * NQ);
        const float4* q1 = (const float4*)(g_Q + PL + (size_t)b * NQ);
        const float4* q2 = (const float4*)(g_Q + 2 * PL + (size_t)b * NQ);
        const float4* q3 = (const float4*)(g_Q + 3 * PL + (size_t)b * NQ);
        float4 a = q0[tid], bq = q1[tid], c = q2[tid], d = q3[tid];
        float4 r;
        r.x = (a.x + bq.x) + (c.x + d.x);
        r.y = (a.y + bq.y) + (c.y + d.y);
        r.z = (a.z + bq.z) + (c.z + d.z);
        r.w = (a.w + bq.w) + (c.w + d.w);
        ((float4*)s_q)[tid] = r;
    }
    {
        const float4* kg = (const float4*)(g_K + (size_t)b * 2048);
        const float4* pg = (const float4*)(g_P + (size_t)b * 2048);
        for (int i4 = tid; i4 < 512; i4 += 256) {
            int t = i4 >> 2, k0 = (i4 & 3) * 4;
            float4 kv = kg[i4], pv = pg[i4];
            s_k[t * 17 + k0] = kv.x; s_k[t * 17 + k0 + 1] = kv.y;
            s_k[t * 17 + k0 + 2] = kv.z; s_k[t * 17 + k0 + 3] = kv.w;
            s_p[t * 17 + k0] = pv.x; s_p[t * 17 + k0 + 1] = pv.y;
            s_p[t * 17 + k0 + 2] = pv.z; s_p[t * 17 + k0 + 3] = pv.w;
        }
    }
    __syncthreads();

    {
        int t = tid & 127, hb = (tid >> 7) * 32;
        float kr[16];
#pragma unroll
        for (int k = 0; k < 16; k++) kr[k] = s_k[t * 17 + k];
        for (int j = 0; j < 32; j++) {
            int h = hb + j;
            float acc = 0.f;
#pragma unroll
            for (int k = 0; k < 16; k++) acc += kr[k] * s_q[h * 16 + k];
            s_s[h * 129 + t] = acc;
        }
    }
    __syncthreads();

    for (int r = 0; r < 8; r++) {
        int h = w * 8 + r;
        float* row = s_s + h * 129;
        float v0 = row[lane], v1 = row[lane + 32], v2 = row[lane + 64], v3 = row[lane + 96];
        float mx = fmaxf(fmaxf(v0, v1), fmaxf(v2, v3));
#pragma unroll
        for (int d = 16; d > 0; d >>= 1) mx = fmaxf(mx, __shfl_xor_sync(0xffffffffu, mx, d));
        float e0 = __expf(v0 - mx), e1 = __expf(v1 - mx), e2 = __expf(v2 - mx), e3 = __expf(v3 - mx);
        float sum = e0 + e1 + e2 + e3;
#pragma unroll
        for (int d = 16; d > 0; d >>= 1) sum += __shfl_xor_sync(0xffffffffu, sum, d);
        float inv = 1.0f / sum;
        row[lane] = e0 * inv; row[lane + 32] = e1 * inv;
        row[lane + 64] = e2 * inv; row[lane + 96] = e3 * inv;
        float tg = inv * (e0 * (float)lane + e1 * (float)(lane + 32)
                        + e2 * (float)(lane + 64) + e3 * (float)(lane + 96));
#pragma unroll
        for (int d = 16; d > 0; d >>= 1) tg += __shfl_xor_sync(0xffffffffu, tg, d);
        if (lane == 0) s_tag[h] = tg;
    }
    __syncthreads();

    // A1-A2 in place (rows 0..31 of s_s)
    for (int i = tid; i < 32 * 128; i += 256) {
        int h = i >> 7, t = i & 127;
        s_s[h * 129 + t] = s_s[h * 129 + t] - s_s[(h + 32) * 129 + t];
    }
    __syncthreads();

    {
        int h = tid >> 3, rg = tid & 7;
        float a0 = 0.f, a1 = 0.f;
        const float* ad = s_s + h * 129;
        for (int t = 0; t < 128; t++) {
            float a = ad[t];
            a0 += a * s_p[t * 17 + 2 * rg];
            a1 += a * s_p[t * 17 + 2 * rg + 1];
        }
        s_r[h * 18 + 2 * rg] = a0;
        s_r[h * 18 + 2 * rg + 1] = a1;
    }
    if (tid < 32) {
        s_r[tid * 18 + 16] = s_tag[tid];
        s_r[tid * 18 + 17] = s_tag[tid + 32];
    }
    __syncthreads();

    {
        const float* wrow = Wh + w * 576;
        float acc = 0.f;
        for (int j = lane; j < 576; j += 32) acc += wrow[j] * s_r[j];
#pragma unroll
        for (int d = 16; d > 0; d >>= 1) acc += __shfl_xor_sync(0xffffffffu, acc, d);
        if (lane == 0) s_r[576 + w] = fmaxf(acc + bh[w], 0.f);
    }
    __syncthreads();

    if (tid == 0) {
        float y[4];
#pragma unroll
        for (int c = 0; c < 4; c++) {
            float acc = by[c];
#pragma unroll
            for (int i = 0; i < 8; i++) acc += Wy[c * 8 + i] * s_r[576 + i];
            y[c] = acc;
        }
        int amax = 0;
#pragma unroll
        for (int c = 1; c < 4; c++) if (y[c] > y[amax]) amax = c;
        if (out_size >= 5 * BATCH) {
            for (int c = 0; c < 4; c++) out[b * 4 + c] = y[c];
            out[4 * BATCH + b] = (float)amax;
        } else if (out_size >= 4 * BATCH) {
            for (int c = 0; c < 4; c++) out[b * 4 + c] = y[c];
        } else if (out_size >= BATCH) {
            out[b] = (float)amax;
        }
    }
}

extern "C" void kernel_launch(void* const* d_in, const int* in_sizes, int n_in,
                              void* d_out, int out_size) {
    const float* z_seq = (const float*)d_in[0];
    const float* W_k   = (const float*)d_in[1];
    const float* W_q1  = (const float*)d_in[2];
    const float* W_q2  = (const float*)d_in[3];
    const float* W_s   = (const float*)d_in[4];
    const float* gamma = (const float*)d_in[5];
    const float* beta  = (const float*)d_in[6];
    const float* W_h   = (const float*)d_in[7];
    const float* b_h   = (const float*)d_in[8];
    const float* W_y   = (const float*)d_in[9];
    const float* b_y   = (const float*)d_in[10];
    float* out = (float*)d_out;

    cudaFuncSetAttribute(kprep,   cudaFuncAttributeMaxDynamicSharedMemorySize, 84480);
    cudaFuncSetAttribute(kgemm,   cudaFuncAttributeMaxDynamicSharedMemorySize, 81920);
    cudaFuncSetAttribute(kattend, cudaFuncAttributeMaxDynamicSharedMemorySize, 57152);

    kprep<<<BATCH + 1024, 256, 84480>>>(z_seq, gamma, beta, W_k, W_s, W_q1, W_q2);
    kgemm<<<2048, 256, 81920>>>();
    kattend<<<8192, 256, 57152>>>(W_h, b_h, W_y, b_y, out, out_size);
}